// round 9
// baseline (speedup 1.0000x reference)
#include <cuda_runtime.h>
#include <cuda_bf16.h>

// B=16384, CLIP=50, D=64, emb_user has NUM_FRIENDS+1=100001 rows, row NUM_FRIENDS all-zero.
#define NUM_FRIENDS 100000
#define CLIP 50
#define NCHUNK 13            // ceil(50/4) chunks of 4 friends
#define DIM 64
#define MAX_B 16384

// Static scratch: s_c * gate_c per (sample, friend). No device allocation allowed.
__device__ float g_sgate[(size_t)MAX_B * CLIP];

__device__ __forceinline__ float fast_sigmoid(float x) {
    return 1.0f / (1.0f + __expf(-x));
}

// ---------------- Kernel 1: one warp per (sample b, chunk t of 4 friends) ----------
// Warp layout: 4 groups of 8 lanes (group = lane>>3); group g handles friend c = t*4+g.
// Lane owns 8 dims: dl = (lane&7)*8. 64-dim dot reduces with 3 intra-group SHFLs.
// Writes gate -> out[B + b*CLIP + c] and s*gate -> g_sgate[b*CLIP + c].
__global__ __launch_bounds__(256)
void gmf_gate_kernel(const int* __restrict__ user_indices,
                     const int* __restrict__ item_indices,
                     const int* __restrict__ user_friend_indices,
                     const float* __restrict__ emb_user,
                     const float* __restrict__ emb_item,
                     const float* __restrict__ affine_w,
                     const float* __restrict__ affine_b,
                     float* __restrict__ out,
                     int B)
{
    const int gw = blockIdx.x * 8 + (threadIdx.x >> 5);   // global warp id
    if (gw >= B * NCHUNK) return;
    const int b = gw / NCHUNK;
    const int t = gw - b * NCHUNK;

    const int lane = threadIdx.x & 31;
    const int g    = lane >> 3;          // friend subgroup 0..3
    const int dl   = (lane & 7) << 3;    // dim base (8 dims per lane)
    const int c    = t * 4 + g;          // friend slot 0..51

    const int u  = __ldg(user_indices + b);
    const int it = __ldg(item_indices + b);

    // Friend id (8-lane broadcast load); slots >= CLIP use the zero padding row.
    const int fi = (c < CLIP) ? __ldg(user_friend_indices + (size_t)u * CLIP + c)
                              : NUM_FRIENDS;

    // ie * w for this lane's 8 dims (L1-resident after first chunk of each sample).
    const float4 ie0 = *reinterpret_cast<const float4*>(emb_item + (size_t)it * DIM + dl);
    const float4 ie1 = *reinterpret_cast<const float4*>(emb_item + (size_t)it * DIM + dl + 4);
    const float4 wv0 = *reinterpret_cast<const float4*>(affine_w + dl);
    const float4 wv1 = *reinterpret_cast<const float4*>(affine_w + dl + 4);
    const float  bb  = __ldg(affine_b);

    const float* row = emb_user + (size_t)fi * DIM + dl;
    const float4 fa = *reinterpret_cast<const float4*>(row);
    const float4 fb = *reinterpret_cast<const float4*>(row + 4);

    // s = dot(fe, ie*w) over this lane's 8 dims, then reduce across the 8-lane group.
    float s = fa.x * (ie0.x * wv0.x) + fa.y * (ie0.y * wv0.y)
            + fa.z * (ie0.z * wv0.z) + fa.w * (ie0.w * wv0.w)
            + fb.x * (ie1.x * wv1.x) + fb.y * (ie1.y * wv1.y)
            + fb.z * (ie1.z * wv1.z) + fb.w * (ie1.w * wv1.w);
    s += __shfl_xor_sync(0xffffffffu, s, 4);
    s += __shfl_xor_sync(0xffffffffu, s, 2);
    s += __shfl_xor_sync(0xffffffffu, s, 1);

    // Padding rows are all-zero -> s==0 -> gate==sigmoid(bb): matches reference exactly.
    const float gate = fast_sigmoid(s + bb);

    if (c < CLIP && (lane & 7) == 0) {
        out[B + (size_t)b * CLIP + c]    = gate;
        g_sgate[(size_t)b * CLIP + c]    = s * gate;
    }
}

// ---------------- Kernel 2: one warp per sample — reduce to rating -----------------
// rating = sigmoid( (sum_c s_c*gate_c) / nreal + b )
__global__ __launch_bounds__(256)
void gmf_rating_kernel(const int* __restrict__ user_indices,
                       const int* __restrict__ user_friend_indices,
                       const float* __restrict__ affine_b,
                       float* __restrict__ out,
                       int B)
{
    const int b = blockIdx.x * 8 + (threadIdx.x >> 5);
    if (b >= B) return;
    const int lane = threadIdx.x & 31;

    const int u = __ldg(user_indices + b);
    const int* fptr = user_friend_indices + (size_t)u * CLIP;

    // Count real friends with two ballots.
    const bool r0 = (lane < CLIP)      && (__ldg(fptr + lane)      != NUM_FRIENDS);
    const bool r1 = (lane + 32 < CLIP) && (__ldg(fptr + lane + 32) != NUM_FRIENDS);
    const int nreal = __popc(__ballot_sync(0xffffffffu, r0))
                    + __popc(__ballot_sync(0xffffffffu, r1));

    const float* sg = g_sgate + (size_t)b * CLIP;
    float part = (lane < CLIP)      ? sg[lane]      : 0.0f;
    part      += (lane + 32 < CLIP) ? sg[lane + 32] : 0.0f;
    #pragma unroll
    for (int o = 16; o > 0; o >>= 1)
        part += __shfl_xor_sync(0xffffffffu, part, o);

    if (lane == 0)
        out[b] = fast_sigmoid(part / (float)nreal + __ldg(affine_b));
}

extern "C" void kernel_launch(void* const* d_in, const int* in_sizes, int n_in,
                              void* d_out, int out_size) {
    const int*   user_indices        = (const int*)  d_in[0];
    const int*   item_indices        = (const int*)  d_in[1];
    const int*   user_friend_indices = (const int*)  d_in[2];
    const float* emb_user            = (const float*)d_in[3];
    const float* emb_item            = (const float*)d_in[4];
    const float* affine_w            = (const float*)d_in[5];
    const float* affine_b            = (const float*)d_in[6];
    float*       out                 = (float*)d_out;

    const int B = in_sizes[0];

    const int warps1  = B * NCHUNK;
    const int blocks1 = (warps1 + 7) / 8;          // 8 warps / 256-thread block
    gmf_gate_kernel<<<blocks1, 256>>>(
        user_indices, item_indices, user_friend_indices,
        emb_user, emb_item, affine_w, affine_b, out, B);

    const int blocks2 = (B + 7) / 8;
    gmf_rating_kernel<<<blocks2, 256>>>(
        user_indices, user_friend_indices, affine_b, out, B);
}

// round 14
// speedup vs baseline: 1.7157x; 1.7157x over previous
#include <cuda_runtime.h>
#include <cuda_bf16.h>

// B=16384, CLIP=50, D=64, emb_user has NUM_FRIENDS+1=100001 rows, row NUM_FRIENDS all-zero.
#define NUM_FRIENDS 100000
#define CLIP 50
#define CLIP_PAD 52          // 13 iterations x 4 friends
#define NITER 13
#define DIM 64
#define WARPS_PER_BLOCK 8

__device__ __forceinline__ float fast_sigmoid(float x) {
    return 1.0f / (1.0f + __expf(-x));
}

// One warp per sample. 4 friend-groups of 8 lanes (group = lane>>3); each lane
// owns 8 dims (two float4s at dl=(lane&7)*8). 64-dim dot reduces with 3 SHFLs
// (xor 4,2,1) inside the group -> every SHFL/MUFU serves 4 friends.
// Identity: logit = sum_c s_c * sigmoid(s_c + b) / nreal + b  (no per-dim
// gated accumulator, no final 64-dim reduce).
// __launch_bounds__(256, 6): cap regs at 42 -> 48 resident warps/SM; we are
// latency-bound, so occupancy is the binding resource.
__global__ __launch_bounds__(WARPS_PER_BLOCK * 32, 6)
void gmf_kernel(const int* __restrict__ user_indices,
                const int* __restrict__ item_indices,
                const int* __restrict__ user_friend_indices,
                const float* __restrict__ emb_user,
                const float* __restrict__ emb_item,
                const float* __restrict__ affine_w,
                const float* __restrict__ affine_b,
                float* __restrict__ out,
                int B)
{
    const int w    = threadIdx.x >> 5;
    const int lane = threadIdx.x & 31;
    const int b    = blockIdx.x * WARPS_PER_BLOCK + w;   // warp-uniform

    __shared__ int s_fi[WARPS_PER_BLOCK][CLIP_PAD];

    if (b >= B) return;

    const int u  = user_indices[b];
    const int it = item_indices[b];

    // Stage friend ids (coalesced 200B) + 2 sentinel pads.
    const int* fptr = user_friend_indices + (size_t)u * CLIP;
    if (lane < CLIP)            s_fi[w][lane]        = __ldg(fptr + lane);
    if (lane + 32 < CLIP)       s_fi[w][lane + 32]   = __ldg(fptr + lane + 32);
    if (lane < CLIP_PAD - CLIP) s_fi[w][CLIP + lane] = NUM_FRIENDS;
    __syncwarp();

    const int g  = lane >> 3;            // friend subgroup 0..3
    const int dl = (lane & 7) << 3;      // dim base 0..56 (8 dims per lane)

    const float4 ie0 = *reinterpret_cast<const float4*>(emb_item + (unsigned)it * DIM + dl);
    const float4 ie1 = *reinterpret_cast<const float4*>(emb_item + (unsigned)it * DIM + dl + 4);
    const float4 wv0 = *reinterpret_cast<const float4*>(affine_w + dl);
    const float4 wv1 = *reinterpret_cast<const float4*>(affine_w + dl + 4);
    const float  bb  = __ldg(affine_b);
    const float4 wiA = make_float4(ie0.x * wv0.x, ie0.y * wv0.y, ie0.z * wv0.z, ie0.w * wv0.w);
    const float4 wiB = make_float4(ie1.x * wv1.x, ie1.y * wv1.y, ie1.z * wv1.z, ie1.w * wv1.w);

    const float* __restrict__ eup  = emb_user + dl;
    float* __restrict__       gout = out + B + (size_t)b * CLIP;

    float sg    = 0.0f;   // sum of s_c * gate_c
    int   nreal = 0;

    // Depth-2 rotating prefetch.
    int f0 = s_fi[w][g];
    int f1 = s_fi[w][4 + g];
    float4 a0 = *reinterpret_cast<const float4*>(eup + (unsigned)f0 * DIM);
    float4 b0 = *reinterpret_cast<const float4*>(eup + (unsigned)f0 * DIM + 4);
    float4 a1 = *reinterpret_cast<const float4*>(eup + (unsigned)f1 * DIM);
    float4 b1 = *reinterpret_cast<const float4*>(eup + (unsigned)f1 * DIM + 4);

    #pragma unroll
    for (int t = 0; t < NITER; t++) {
        int fn = NUM_FRIENDS;
        float4 an = make_float4(0.f, 0.f, 0.f, 0.f);
        float4 bn = make_float4(0.f, 0.f, 0.f, 0.f);
        if (t + 2 < NITER) {
            fn = s_fi[w][(t + 2) * 4 + g];
            an = *reinterpret_cast<const float4*>(eup + (unsigned)fn * DIM);
            bn = *reinterpret_cast<const float4*>(eup + (unsigned)fn * DIM + 4);
        }

        nreal += (f0 != NUM_FRIENDS);

        // dot(fe, ie*w): two independent FFMA chains, then 3-SHFL group reduce.
        float sA = a0.x * wiA.x + a0.y * wiA.y + a0.z * wiA.z + a0.w * wiA.w;
        float sB = b0.x * wiB.x + b0.y * wiB.y + b0.z * wiB.z + b0.w * wiB.w;
        float s  = sA + sB;
        s += __shfl_xor_sync(0xffffffffu, s, 4);
        s += __shfl_xor_sync(0xffffffffu, s, 2);
        s += __shfl_xor_sync(0xffffffffu, s, 1);

        // Padding rows are all-zero -> s==0 -> gate==sigmoid(bb) (reference-exact);
        // s*gate contributes 0.
        const float gate = fast_sigmoid(s + bb);
        sg = fmaf(s, gate, sg);

        // Direct gate store: lanes 0,8,16,24 write friends 4t..4t+3 — one 16B
        // segment per warp-iteration. Slots 50,51 (t=12, g>=2) are suppressed.
        const int c = t * 4 + g;
        if ((lane & 7) == 0 && c < CLIP)
            gout[c] = gate;

        f0 = f1; a0 = a1; b0 = b1;
        f1 = fn; a1 = an; b1 = bn;
    }

    // sg / nreal are uniform within each 8-lane group; combine the 4 groups.
    sg += __shfl_xor_sync(0xffffffffu, sg, 8);
    sg += __shfl_xor_sync(0xffffffffu, sg, 16);
    nreal += __shfl_xor_sync(0xffffffffu, nreal, 8);
    nreal += __shfl_xor_sync(0xffffffffu, nreal, 16);

    if (lane == 0)
        out[b] = fast_sigmoid(sg / (float)nreal + bb);
}

extern "C" void kernel_launch(void* const* d_in, const int* in_sizes, int n_in,
                              void* d_out, int out_size) {
    const int*   user_indices        = (const int*)  d_in[0];
    const int*   item_indices        = (const int*)  d_in[1];
    const int*   user_friend_indices = (const int*)  d_in[2];
    const float* emb_user            = (const float*)d_in[3];
    const float* emb_item            = (const float*)d_in[4];
    const float* affine_w            = (const float*)d_in[5];
    const float* affine_b            = (const float*)d_in[6];
    float*       out                 = (float*)d_out;

    const int B = in_sizes[0];
    const int blocks = (B + WARPS_PER_BLOCK - 1) / WARPS_PER_BLOCK;
    gmf_kernel<<<blocks, WARPS_PER_BLOCK * 32>>>(
        user_indices, item_indices, user_friend_indices,
        emb_user, emb_item, affine_w, affine_b, out, B);
}